// round 8
// baseline (speedup 1.0000x reference)
#include <cuda_runtime.h>
#include <math.h>

// ---------------- problem constants ----------------
#define D_MODEL 1024
#define D_FF    4096
#define NB      2
#define SEQ     2048
#define NH      16
#define DK      64
#define M_TOT   (NB*SEQ)          // 4096 rows

// ---------------- scratch (static device arrays; no allocations) ----------------
__device__ float g_q  [M_TOT * D_MODEL];   // [B,H,S,DK]
__device__ float g_k  [M_TOT * D_MODEL];   // [B,H,S,DK]
__device__ float g_v  [M_TOT * D_MODEL];   // [B,H,S,DK]
__device__ float g_ctx[M_TOT * D_MODEL];   // [B,S,D]
__device__ float g_t  [M_TOT * D_MODEL];   // residual sums
__device__ float g_x  [M_TOT * D_MODEL];   // LN1 output (kept for FFN residual)
__device__ float g_h  [M_TOT * D_FF];      // FFN hidden

// ---------------- generic tiled SGEMM: C = A[MxK] @ B[KxN] (+bias/relu/res/scatter) ----------------
#define BM 128
#define BN 128
#define BK 16

enum { MODE_BIAS = 0, MODE_QKV = 1, MODE_RELU = 2, MODE_RES = 3 };

template<int MODE>
__global__ __launch_bounds__(256, 2)
void gemm_kernel(const float* __restrict__ A, const float* __restrict__ Bm,
                 const float* __restrict__ bias, const float* __restrict__ Res,
                 float* __restrict__ C, int M, int N, int K)
{
    __shared__ __align__(16) float As[2][BK][BM];
    __shared__ __align__(16) float Bs[2][BK][BN];

    const int t  = threadIdx.x;
    const int tx = t & 15;
    const int ty = t >> 4;
    const int n0 = blockIdx.x * BN;
    const int m0 = blockIdx.y * BM;

    // global-load assignments (all dims are multiples of 128/16: no guards needed)
    const int a_row = t >> 2;            // 0..63 (plus +64 twin)
    const int a_k   = (t & 3) << 2;      // 0,4,8,12
    const int b_k   = t >> 5;            // 0..7 (plus +8 twin)
    const int b_n   = (t & 31) << 2;     // 0..124

    float4 av0, av1, bv0, bv1;

#define FETCH(KT) do {                                                        \
    const float* Ap = A + (size_t)(m0 + a_row) * K + (size_t)(KT)*BK + a_k;   \
    av0 = *(const float4*)Ap;                                                 \
    av1 = *(const float4*)(Ap + (size_t)64 * K);                              \
    const float* Bp = Bm + (size_t)((KT)*BK + b_k) * N + n0 + b_n;            \
    bv0 = *(const float4*)Bp;                                                 \
    bv1 = *(const float4*)(Bp + (size_t)8 * N);                               \
} while (0)

#define STASH(BUF) do {                                                       \
    As[BUF][a_k+0][a_row]    = av0.x;                                         \
    As[BUF][a_k+1][a_row]    = av0.y;                                         \
    As[BUF][a_k+2][a_row]    = av0.z;                                         \
    As[BUF][a_k+3][a_row]    = av0.w;                                         \
    As[BUF][a_k+0][a_row+64] = av1.x;                                         \
    As[BUF][a_k+1][a_row+64] = av1.y;                                         \
    As[BUF][a_k+2][a_row+64] = av1.z;                                         \
    As[BUF][a_k+3][a_row+64] = av1.w;                                         \
    *(float4*)&Bs[BUF][b_k][b_n]   = bv0;                                     \
    *(float4*)&Bs[BUF][b_k+8][b_n] = bv1;                                     \
} while (0)

    FETCH(0);
    STASH(0);
    __syncthreads();

    float acc[8][8];
    #pragma unroll
    for (int i = 0; i < 8; i++)
        #pragma unroll
        for (int j = 0; j < 8; j++) acc[i][j] = 0.f;

    const int ntiles = K / BK;
    for (int kt = 0; kt < ntiles; kt++) {
        const int buf = kt & 1;
        if (kt + 1 < ntiles) FETCH(kt + 1);
        #pragma unroll
        for (int k = 0; k < BK; k++) {
            float4 a0 = *(const float4*)&As[buf][k][ty * 4];
            float4 a1 = *(const float4*)&As[buf][k][64 + ty * 4];
            float4 b0 = *(const float4*)&Bs[buf][k][tx * 4];
            float4 b1 = *(const float4*)&Bs[buf][k][64 + tx * 4];
            float af[8] = {a0.x, a0.y, a0.z, a0.w, a1.x, a1.y, a1.z, a1.w};
            float bf[8] = {b0.x, b0.y, b0.z, b0.w, b1.x, b1.y, b1.z, b1.w};
            #pragma unroll
            for (int i = 0; i < 8; i++)
                #pragma unroll
                for (int j = 0; j < 8; j++)
                    acc[i][j] = fmaf(af[i], bf[j], acc[i][j]);
        }
        if (kt + 1 < ntiles) STASH(buf ^ 1);
        __syncthreads();
    }
#undef FETCH
#undef STASH

    // epilogue (vectorized float4 stores)
    #pragma unroll
    for (int i = 0; i < 8; i++) {
        const int row = m0 + (ty << 2) + (i & 3) + ((i >> 2) << 6);
        #pragma unroll
        for (int jj = 0; jj < 2; jj++) {
            const int col = n0 + (tx << 2) + (jj << 6);
            float4 bvv = *(const float4*)&bias[col];
            float4 r;
            r.x = acc[i][jj * 4 + 0] + bvv.x;
            r.y = acc[i][jj * 4 + 1] + bvv.y;
            r.z = acc[i][jj * 4 + 2] + bvv.z;
            r.w = acc[i][jj * 4 + 3] + bvv.w;
            if (MODE == MODE_RELU) {
                r.x = fmaxf(r.x, 0.f); r.y = fmaxf(r.y, 0.f);
                r.z = fmaxf(r.z, 0.f); r.w = fmaxf(r.w, 0.f);
            }
            if (MODE == MODE_RES) {
                float4 rv = *(const float4*)&Res[(size_t)row * N + col];
                r.x += rv.x; r.y += rv.y; r.z += rv.z; r.w += rv.w;
            }
            if (MODE == MODE_QKV) {
                // scatter into [B,H,S,DK]
                const int h  = col >> 6;
                const int d  = col & 63;
                const int bb = row >> 11;    // row / SEQ
                const int ss = row & 2047;   // row % SEQ
                *(float4*)&C[((size_t)(bb * NH + h) * SEQ + ss) * DK + d] = r;
            } else {
                *(float4*)&C[(size_t)row * N + col] = r;
            }
        }
    }
}

// ---------------- flash attention (causal, strict j < i; row 0 zeroed) ----------------
#define AST 68                 // padded smem stride (floats), keeps float4 alignment
#define ATTN_SMEM (4 * 64 * AST * (int)sizeof(float))   // Qs,KsT,Vs,Ps = 69632 B

__device__ __forceinline__ float rmax16(float v) {
    #pragma unroll
    for (int o = 8; o; o >>= 1) v = fmaxf(v, __shfl_xor_sync(0xffffffffu, v, o));
    return v;
}
__device__ __forceinline__ float rsum16(float v) {
    #pragma unroll
    for (int o = 8; o; o >>= 1) v += __shfl_xor_sync(0xffffffffu, v, o);
    return v;
}

__global__ __launch_bounds__(256, 2)
void attn_kernel(const float* __restrict__ Q, const float* __restrict__ Kg,
                 const float* __restrict__ Vg, float* __restrict__ ctx)
{
    extern __shared__ float sm[];
    float* Qs  = sm;                 // [64][AST]  (pre-scaled by 1/8)
    float* KsT = sm + 64 * AST;      // [d][c] transposed
    float* Vs  = sm + 2 * 64 * AST;  // [k][d]
    float* Ps  = sm + 3 * 64 * AST;  // [q][k]

    const int t  = threadIdx.x;
    const int tr = t >> 4;           // 0..15 -> 4 query rows each
    const int tc = t & 15;           // 0..15 -> 4 cols each
    const int qt = blockIdx.x;       // query tile
    const int bh = blockIdx.y;       // b*NH + h
    const int q0 = qt * 64;

    const float* Qb = Q  + (size_t)bh * SEQ * DK;
    const float* Kb = Kg + (size_t)bh * SEQ * DK;
    const float* Vb = Vg + (size_t)bh * SEQ * DK;

    // load Q tile, scaled by 1/sqrt(DK)=0.125
    {
        const int r  = t >> 2;
        const int db = (t & 3) * 16;
        #pragma unroll
        for (int u = 0; u < 4; u++) {
            float4 v = *(const float4*)&Qb[(size_t)(q0 + r) * DK + db + 4 * u];
            v.x *= 0.125f; v.y *= 0.125f; v.z *= 0.125f; v.w *= 0.125f;
            *(float4*)&Qs[r * AST + db + 4 * u] = v;
        }
    }

    float o[4][4];
    float m[4], l[4];
    #pragma unroll
    for (int i = 0; i < 4; i++) {
        m[i] = -1e30f; l[i] = 0.f;
        #pragma unroll
        for (int j = 0; j < 4; j++) o[i][j] = 0.f;
    }

    for (int kt = 0; kt <= qt; kt++) {
        // load K (transposed) and V tiles
        {
            const int r  = t >> 2;
            const int db = (t & 3) * 16;
            const size_t gb = (size_t)(kt * 64 + r) * DK + db;
            #pragma unroll
            for (int u = 0; u < 4; u++) {
                float4 kv = *(const float4*)&Kb[gb + 4 * u];
                KsT[(db + 4 * u + 0) * AST + r] = kv.x;
                KsT[(db + 4 * u + 1) * AST + r] = kv.y;
                KsT[(db + 4 * u + 2) * AST + r] = kv.z;
                KsT[(db + 4 * u + 3) * AST + r] = kv.w;
                float4 vv = *(const float4*)&Vb[gb + 4 * u];
                *(float4*)&Vs[r * AST + db + 4 * u] = vv;
            }
        }
        __syncthreads();

        // S = Qs @ KsT  (each thread: 4 rows x 4 cols)
        float sc[4][4];
        #pragma unroll
        for (int i = 0; i < 4; i++)
            #pragma unroll
            for (int j = 0; j < 4; j++) sc[i][j] = 0.f;

        #pragma unroll
        for (int d4 = 0; d4 < 16; d4++) {
            float qf[4][4];
            #pragma unroll
            for (int i = 0; i < 4; i++) {
                float4 qv = *(const float4*)&Qs[(4 * tr + i) * AST + 4 * d4];
                qf[i][0] = qv.x; qf[i][1] = qv.y; qf[i][2] = qv.z; qf[i][3] = qv.w;
            }
            #pragma unroll
            for (int u = 0; u < 4; u++) {
                float4 kv = *(const float4*)&KsT[(4 * d4 + u) * AST + 4 * tc];
                #pragma unroll
                for (int i = 0; i < 4; i++) {
                    sc[i][0] = fmaf(qf[i][u], kv.x, sc[i][0]);
                    sc[i][1] = fmaf(qf[i][u], kv.y, sc[i][1]);
                    sc[i][2] = fmaf(qf[i][u], kv.z, sc[i][2]);
                    sc[i][3] = fmaf(qf[i][u], kv.w, sc[i][3]);
                }
            }
        }

        // causal mask: key j allowed iff j < qi (strict)
        {
            const int kjb = kt * 64 + 4 * tc;
            #pragma unroll
            for (int i = 0; i < 4; i++) {
                const int qi = q0 + 4 * tr + i;
                #pragma unroll
                for (int j = 0; j < 4; j++)
                    if (kjb + j >= qi) sc[i][j] = -1e30f;
            }
        }

        // online softmax update + write P
        #pragma unroll
        for (int i = 0; i < 4; i++) {
            float mx = fmaxf(fmaxf(sc[i][0], sc[i][1]), fmaxf(sc[i][2], sc[i][3]));
            mx = rmax16(mx);
            const float mnew = fmaxf(m[i], mx);
            const float corr = __expf(m[i] - mnew);
            m[i] = mnew;
            float4 p;
            p.x = __expf(sc[i][0] - mnew);
            p.y = __expf(sc[i][1] - mnew);
            p.z = __expf(sc[i][2] - mnew);
            p.w = __expf(sc[i][3] - mnew);
            float rs = p.x + p.y + p.z + p.w;
            rs = rsum16(rs);
            l[i] = l[i] * corr + rs;
            #pragma unroll
            for (int j = 0; j < 4; j++) o[i][j] *= corr;
            *(float4*)&Ps[(4 * tr + i) * AST + 4 * tc] = p;
        }
        __syncthreads();

        // O += P @ V
        #pragma unroll
        for (int k4 = 0; k4 < 16; k4++) {
            float pf[4][4];
            #pragma unroll
            for (int i = 0; i < 4; i++) {
                float4 pv = *(const float4*)&Ps[(4 * tr + i) * AST + 4 * k4];
                pf[i][0] = pv.x; pf[i][1] = pv.y; pf[i][2] = pv.z; pf[i][3] = pv.w;
            }
            #pragma unroll
            for (int u = 0; u < 4; u++) {
                float4 vv = *(const float4*)&Vs[(4 * k4 + u) * AST + 4 * tc];
                #pragma unroll
                for (int i = 0; i < 4; i++) {
                    o[i][0] = fmaf(pf[i][u], vv.x, o[i][0]);
                    o[i][1] = fmaf(pf[i][u], vv.y, o[i][1]);
                    o[i][2] = fmaf(pf[i][u], vv.z, o[i][2]);
                    o[i][3] = fmaf(pf[i][u], vv.w, o[i][3]);
                }
            }
        }
        __syncthreads();
    }

    // write ctx in [B,S,D] layout; row 0 (fully masked) is zeroed like the reference
    const int b = bh >> 4, h = bh & 15;
    #pragma unroll
    for (int i = 0; i < 4; i++) {
        const int qi = q0 + 4 * tr + i;
        const float inv = (qi == 0) ? 0.f : (1.f / l[i]);
        float4 r;
        r.x = o[i][0] * inv; r.y = o[i][1] * inv;
        r.z = o[i][2] * inv; r.w = o[i][3] * inv;
        *(float4*)&ctx[((size_t)(b * SEQ + qi)) * D_MODEL + h * DK + 4 * tc] = r;
    }
}

// ---------------- layernorm (one block per row of 1024) ----------------
__global__ __launch_bounds__(256)
void ln_kernel(const float* __restrict__ X, const float* __restrict__ G,
               const float* __restrict__ Bt, float* __restrict__ O)
{
    __shared__ float ws[8], ws2[8];
    __shared__ float s_mu, s_rs;
    const int t = threadIdx.x;
    const size_t row = blockIdx.x;

    float4 v = *(const float4*)&X[row * D_MODEL + t * 4];
    float s  = v.x + v.y + v.z + v.w;
    float s2 = v.x * v.x + v.y * v.y + v.z * v.z + v.w * v.w;
    #pragma unroll
    for (int o = 16; o; o >>= 1) {
        s  += __shfl_xor_sync(0xffffffffu, s,  o);
        s2 += __shfl_xor_sync(0xffffffffu, s2, o);
    }
    if ((t & 31) == 0) { ws[t >> 5] = s; ws2[t >> 5] = s2; }
    __syncthreads();
    if (t == 0) {
        float S = 0.f, S2 = 0.f;
        #pragma unroll
        for (int w = 0; w < 8; w++) { S += ws[w]; S2 += ws2[w]; }
        const float mu  = S * (1.f / (float)D_MODEL);
        const float var = S2 * (1.f / (float)D_MODEL) - mu * mu;
        s_mu = mu;
        s_rs = rsqrtf(var + 1e-5f);
    }
    __syncthreads();
    const float mu = s_mu, rs = s_rs;

    float4 g = *(const float4*)&G[t * 4];
    float4 b = *(const float4*)&Bt[t * 4];
    float4 r;
    r.x = (v.x - mu) * rs * g.x + b.x;
    r.y = (v.y - mu) * rs * g.y + b.y;
    r.z = (v.z - mu) * rs * g.z + b.z;
    r.w = (v.w - mu) * rs * g.w + b.w;
    *(float4*)&O[row * D_MODEL + t * 4] = r;
}

// ---------------- orchestration ----------------
extern "C" void kernel_launch(void* const* d_in, const int* in_sizes, int n_in,
                              void* d_out, int out_size)
{
    (void)in_sizes; (void)n_in; (void)out_size;

    const float* query = (const float*)d_in[0];
    const float* key_i = (const float*)d_in[1];
    const float* vals  = (const float*)d_in[2];
    const float* Wq = (const float*)d_in[3];
    const float* bq = (const float*)d_in[4];
    const float* Wk = (const float*)d_in[5];
    const float* bk = (const float*)d_in[6];
    const float* Wv = (const float*)d_in[7];
    const float* bv = (const float*)d_in[8];
    const float* Wo = (const float*)d_in[9];
    const float* bo = (const float*)d_in[10];
    const float* ln1g = (const float*)d_in[11];
    const float* ln1b = (const float*)d_in[12];
    const float* W1 = (const float*)d_in[13];
    const float* b1 = (const float*)d_in[14];
    const float* W2 = (const float*)d_in[15];
    const float* b2 = (const float*)d_in[16];
    const float* ln2g = (const float*)d_in[17];
    const float* ln2b = (const float*)d_in[18];
    float* out = (float*)d_out;

    float *pq, *pk, *pv, *pctx, *pt, *px, *ph;
    cudaGetSymbolAddress((void**)&pq,   g_q);
    cudaGetSymbolAddress((void**)&pk,   g_k);
    cudaGetSymbolAddress((void**)&pv,   g_v);
    cudaGetSymbolAddress((void**)&pctx, g_ctx);
    cudaGetSymbolAddress((void**)&pt,   g_t);
    cudaGetSymbolAddress((void**)&px,   g_x);
    cudaGetSymbolAddress((void**)&ph,   g_h);

    cudaFuncSetAttribute(attn_kernel,
                         cudaFuncAttributeMaxDynamicSharedMemorySize, ATTN_SMEM);

    const dim3 blk(256);
    const dim3 grid_1k(D_MODEL / BN, M_TOT / BM);   // (8, 32)
    const dim3 grid_4k(D_FF / BN,    M_TOT / BM);   // (32, 32)

    // QKV projections, scattered into [B,H,S,DK]
    gemm_kernel<MODE_QKV><<<grid_1k, blk>>>(query, Wq, bq, nullptr, pq, M_TOT, D_MODEL, D_MODEL);
    gemm_kernel<MODE_QKV><<<grid_1k, blk>>>(key_i, Wk, bk, nullptr, pk, M_TOT, D_MODEL, D_MODEL);
    gemm_kernel<MODE_QKV><<<grid_1k, blk>>>(vals,  Wv, bv, nullptr, pv, M_TOT, D_MODEL, D_MODEL);

    // causal flash attention -> ctx [B,S,D]
    attn_kernel<<<dim3(SEQ / 64, NB * NH), blk, ATTN_SMEM>>>(pq, pk, pv, pctx);

    // attn_out = ctx @ Wo + bo ; fused residual (+query) -> g_t ; LN1 -> g_x
    gemm_kernel<MODE_RES><<<grid_1k, blk>>>(pctx, Wo, bo, query, pt, M_TOT, D_MODEL, D_MODEL);
    ln_kernel<<<M_TOT, 256>>>(pt, ln1g, ln1b, px);

    // FFN: h = relu(x @ W1 + b1) ; y = h @ W2 + b2 + x ; LN2 -> out
    gemm_kernel<MODE_RELU><<<grid_4k, blk>>>(px, W1, b1, nullptr, ph, M_TOT, D_FF, D_MODEL);
    gemm_kernel<MODE_RES><<<grid_1k, blk>>>(ph, W2, b2, px, pt, M_TOT, D_MODEL, D_FF);
    ln_kernel<<<M_TOT, 256>>>(pt, ln2g, ln2b, out);
}

// round 12
// speedup vs baseline: 1.8821x; 1.8821x over previous
#include <cuda_runtime.h>
#include <cuda_bf16.h>
#include <cstdint>
#include <math.h>

// ---------------- problem constants ----------------
#define D_MODEL 1024
#define D_FF    4096
#define NB      2
#define SEQ     2048
#define NH      16
#define DK      64
#define M_TOT   (NB*SEQ)          // 4096 rows

enum { MODE_BIAS = 0, MODE_QKV = 1, MODE_RELU = 2, MODE_RES = 3 };

// ---------------- scratch (static device arrays; no allocations) ----------------
__device__ float g_q  [M_TOT * D_MODEL];   // [B,H,S,DK]
__device__ float g_k  [M_TOT * D_MODEL];
__device__ float g_v  [M_TOT * D_MODEL];
__device__ float g_ctx[M_TOT * D_MODEL];   // [B,S,D]
__device__ float g_t  [M_TOT * D_MODEL];   // residual sums
__device__ float g_x  [M_TOT * D_MODEL];   // LN1 output
__device__ float g_h  [M_TOT * D_FF];      // FFN hidden
// bf16 split operand buffers (reused sequentially by every GEMM)
__device__ __nv_bfloat16 g_abuf[(size_t)M_TOT * 3 * D_FF];    // up to 4096 x 12288
__device__ __nv_bfloat16 g_wbuf[(size_t)D_FF * 3 * D_MODEL];  // up to 4096 x 3072

// ================= PTX helpers (baseline ISA only: sm_80/90 features) =================
__device__ __forceinline__ uint32_t smem_u32(const void* p) {
    uint32_t a;
    asm("{ .reg .u64 t; cvta.to.shared.u64 t, %1; cvt.u32.u64 %0, t; }" : "=r"(a) : "l"(p));
    return a;
}
__device__ __forceinline__ void cp_async16(uint32_t sdst, const void* gsrc) {
    asm volatile("cp.async.cg.shared.global [%0], [%1], 16;" :: "r"(sdst), "l"(gsrc));
}
#define CP_COMMIT() asm volatile("cp.async.commit_group;" ::: "memory")
#define CP_WAIT2()  asm volatile("cp.async.wait_group 2;" ::: "memory")

#define SMEM_SWIZZLE_128B(off) ((off) ^ (((off) >> 3) & 0x70))

#define LDSM_X4(r, addr)                                                        \
    asm volatile("ldmatrix.sync.aligned.m8n8.x4.shared.b16 {%0,%1,%2,%3}, [%4];" \
                 : "=r"((r)[0]), "=r"((r)[1]), "=r"((r)[2]), "=r"((r)[3])        \
                 : "r"(addr))

__device__ __forceinline__ void mma_bf16(float* c, const uint32_t* a,
                                         uint32_t b0, uint32_t b1) {
    asm volatile("mma.sync.aligned.m16n8k16.row.col.f32.bf16.bf16.f32 "
                 "{%0,%1,%2,%3}, {%4,%5,%6,%7}, {%8,%9}, {%0,%1,%2,%3};"
                 : "+f"(c[0]), "+f"(c[1]), "+f"(c[2]), "+f"(c[3])
                 : "r"(a[0]), "r"(a[1]), "r"(a[2]), "r"(a[3]), "r"(b0), "r"(b1));
}

// ================= split-precision conversion kernels =================
// A' row = [A_hi | A_lo | A_hi]  (M x 3K), bf16
__global__ __launch_bounds__(256)
void act_split_kernel(const float* __restrict__ X, __nv_bfloat16* __restrict__ Y,
                      int K, int total4)
{
    int i = blockIdx.x * 256 + threadIdx.x;
    if (i >= total4) return;
    int idx = i << 2;
    float4 v = *(const float4*)&X[idx];
    int m = idx / K, k = idx - m * K;
    __nv_bfloat16 hi4[4], lo4[4];
    hi4[0] = __float2bfloat16(v.x); lo4[0] = __float2bfloat16(v.x - __bfloat162float(hi4[0]));
    hi4[1] = __float2bfloat16(v.y); lo4[1] = __float2bfloat16(v.y - __bfloat162float(hi4[1]));
    hi4[2] = __float2bfloat16(v.z); lo4[2] = __float2bfloat16(v.z - __bfloat162float(hi4[2]));
    hi4[3] = __float2bfloat16(v.w); lo4[3] = __float2bfloat16(v.w - __bfloat162float(hi4[3]));
    size_t base = (size_t)m * 3 * K + k;
    *(uint2*)&Y[base]         = *(uint2*)hi4;
    *(uint2*)&Y[base + K]     = *(uint2*)lo4;
    *(uint2*)&Y[base + 2 * K] = *(uint2*)hi4;
}

// W [K,N] fp32 -> Y [N,3K] bf16 transposed: row = [B_hi | B_hi | B_lo]
__global__ __launch_bounds__(256)
void wt_split_kernel(const float* __restrict__ W, __nv_bfloat16* __restrict__ Y,
                     int K, int N)
{
    __shared__ float tile[32][33];
    const int tx = threadIdx.x & 31, ty = threadIdx.x >> 5;   // ty 0..7
    const int k0 = blockIdx.x * 32, n0 = blockIdx.y * 32;
    #pragma unroll
    for (int u = 0; u < 4; u++)
        tile[ty + 8 * u][tx] = W[(size_t)(k0 + ty + 8 * u) * N + n0 + tx];
    __syncthreads();
    #pragma unroll
    for (int u = 0; u < 4; u++) {
        const int n = n0 + ty + 8 * u;
        const float x = tile[tx][ty + 8 * u];
        const __nv_bfloat16 h = __float2bfloat16(x);
        const __nv_bfloat16 l = __float2bfloat16(x - __bfloat162float(h));
        const size_t base = (size_t)n * 3 * K + (k0 + tx);
        Y[base]         = h;
        Y[base + K]     = h;
        Y[base + 2 * K] = l;
    }
}

// ================= HMMA bf16 GEMM: C[M,N] = A'[M,Kp] @ B'[N,Kp]^T =================
// 128x128 CTA tile, 8 warps (2x4 -> 64x32 per warp), K-chunk = 64 bf16
// (128 B per row, SW128 swizzle), 3-stage cp.async pipeline.
#define GS          3
#define TILE_AB     16384                 // 128 rows x 128 bytes
#define STAGE_BYTES (2 * TILE_AB)
#define GEMM_SMEM   (GS * STAGE_BYTES)    // 98304 B

template<int MODE>
__global__ __launch_bounds__(256, 2)
void tc_gemm(const __nv_bfloat16* __restrict__ A, const __nv_bfloat16* __restrict__ Bw,
             const float* __restrict__ bias, const float* __restrict__ Res,
             float* __restrict__ C, int N, int Kp)
{
    extern __shared__ __align__(1024) char smem[];
    const uint32_t tiles = smem_u32(smem);
    const int t    = threadIdx.x;
    const int lane = t & 31;
    const int wid  = t >> 5;
    const int wm   = wid >> 2;          // 0..1  (64 rows)
    const int wn   = wid & 3;           // 0..3  (32 cols)
    const int n0   = blockIdx.x * 128;
    const int m0   = blockIdx.y * 128;

#define LOAD_CHUNK(CH, ST) do {                                                        \
    const size_t kb = (size_t)(CH) * 128;                                              \
    const uint32_t aB = tiles + (ST) * STAGE_BYTES;                                    \
    const uint32_t bB = aB + TILE_AB;                                                  \
    _Pragma("unroll")                                                                  \
    for (int u = 0; u < 4; u++) {                                                      \
        const int idx = t + 256 * u;                                                   \
        const int row = idx >> 3;                                                      \
        const int c8  = (idx & 7) << 4;                                                \
        const uint32_t sw = SMEM_SWIZZLE_128B((uint32_t)(row * 128 + c8));             \
        cp_async16(aB + sw, (const char*)A  + (size_t)(m0 + row) * (size_t)Kp * 2 + kb + c8); \
        cp_async16(bB + sw, (const char*)Bw + (size_t)(n0 + row) * (size_t)Kp * 2 + kb + c8); \
    }                                                                                  \
    CP_COMMIT();                                                                       \
} while (0)

    const int nch = Kp >> 6;
    #pragma unroll
    for (int p = 0; p < GS; p++) LOAD_CHUNK(p, p);

    float acc[4][4][4];
    #pragma unroll
    for (int mt = 0; mt < 4; mt++)
        #pragma unroll
        for (int nt = 0; nt < 4; nt++)
            #pragma unroll
            for (int r = 0; r < 4; r++) acc[mt][nt][r] = 0.f;

    // ldmatrix lane address components (constant across chunks)
    const int a_row = wm * 64 + (lane & 15);           // + mt*16
    const int a_kb  = (lane >> 4) << 4;                // + ks*32  (bytes)
    const int b_row = wn * 32 + (lane & 7) + ((lane >> 4) << 3);   // + nt2*16
    const int b_kb  = ((lane >> 3) & 1) << 4;          // + ks*32  (bytes)

    #pragma unroll 1
    for (int c = 0; c < nch; c++) {
        const int st = c % GS;
        CP_WAIT2();
        __syncthreads();

        const uint32_t aB = tiles + st * STAGE_BYTES;
        const uint32_t bB = aB + TILE_AB;

        #pragma unroll
        for (int ks = 0; ks < 4; ks++) {
            uint32_t af[4][4];
            #pragma unroll
            for (int mt = 0; mt < 4; mt++) {
                const uint32_t off = SMEM_SWIZZLE_128B(
                    (uint32_t)((a_row + mt * 16) * 128 + ks * 32 + a_kb));
                LDSM_X4(af[mt], aB + off);
            }
            uint32_t bf[2][4];
            #pragma unroll
            for (int nt2 = 0; nt2 < 2; nt2++) {
                const uint32_t off = SMEM_SWIZZLE_128B(
                    (uint32_t)((b_row + nt2 * 16) * 128 + ks * 32 + b_kb));
                LDSM_X4(bf[nt2], bB + off);
            }
            #pragma unroll
            for (int mt = 0; mt < 4; mt++)
                #pragma unroll
                for (int nt = 0; nt < 4; nt++)
                    mma_bf16(acc[mt][nt], af[mt],
                             bf[nt >> 1][(nt & 1) * 2], bf[nt >> 1][(nt & 1) * 2 + 1]);
        }

        __syncthreads();
        if (c + GS < nch) LOAD_CHUNK(c + GS, st);
        else              CP_COMMIT();   // keep per-thread group count invariant
    }
#undef LOAD_CHUNK

    // ---------------- epilogue ----------------
    const int qr = lane >> 2;          // 0..7
    const int qc = (lane & 3) << 1;    // 0,2,4,6
    #pragma unroll
    for (int mt = 0; mt < 4; mt++) {
        #pragma unroll
        for (int nt = 0; nt < 4; nt++) {
            const int col = n0 + wn * 32 + nt * 8 + qc;
            const float2 bv = *(const float2*)&bias[col];
            #pragma unroll
            for (int half = 0; half < 2; half++) {
                const int row = m0 + wm * 64 + mt * 16 + qr + half * 8;
                float2 r;
                r.x = acc[mt][nt][half * 2 + 0] + bv.x;
                r.y = acc[mt][nt][half * 2 + 1] + bv.y;
                if (MODE == MODE_RELU) {
                    r.x = fmaxf(r.x, 0.f); r.y = fmaxf(r.y, 0.f);
                }
                if (MODE == MODE_RES) {
                    float2 rv = *(const float2*)&Res[(size_t)row * N + col];
                    r.x += rv.x; r.y += rv.y;
                }
                if (MODE == MODE_QKV) {
                    const int h = col >> 6, d = col & 63;
                    const int bb = row >> 11, ss = row & 2047;
                    *(float2*)&C[((size_t)(bb * NH + h) * SEQ + ss) * DK + d] = r;
                } else {
                    *(float2*)&C[(size_t)row * N + col] = r;
                }
            }
        }
    }
}

// ---------------- flash attention (causal, strict j < i; row 0 zeroed) ----------------
#define AST 68
#define ATTN_SMEM (4 * 64 * AST * (int)sizeof(float))

__device__ __forceinline__ float rmax16(float v) {
    #pragma unroll
    for (int o = 8; o; o >>= 1) v = fmaxf(v, __shfl_xor_sync(0xffffffffu, v, o));
    return v;
}
__device__ __forceinline__ float rsum16(float v) {
    #pragma unroll
    for (int o = 8; o; o >>= 1) v += __shfl_xor_sync(0xffffffffu, v, o);
    return v;
}

__global__ __launch_bounds__(256, 2)
void attn_kernel(const float* __restrict__ Q, const float* __restrict__ Kg,
                 const float* __restrict__ Vg, float* __restrict__ ctx)
{
    extern __shared__ float sm[];
    float* Qs  = sm;
    float* KsT = sm + 64 * AST;
    float* Vs  = sm + 2 * 64 * AST;
    float* Ps  = sm + 3 * 64 * AST;

    const int t  = threadIdx.x;
    const int tr = t >> 4;
    const int tc = t & 15;
    const int qt = gridDim.x - 1 - blockIdx.x;   // longest tiles first
    const int bh = blockIdx.y;
    const int q0 = qt * 64;

    const float* Qb = Q  + (size_t)bh * SEQ * DK;
    const float* Kb = Kg + (size_t)bh * SEQ * DK;
    const float* Vb = Vg + (size_t)bh * SEQ * DK;

    {
        const int r  = t >> 2;
        const int db = (t & 3) * 16;
        #pragma unroll
        for (int u = 0; u < 4; u++) {
            float4 v = *(const float4*)&Qb[(size_t)(q0 + r) * DK + db + 4 * u];
            v.x *= 0.125f; v.y *= 0.125f; v.z *= 0.125f; v.w *= 0.125f;
            *(float4*)&Qs[r * AST + db + 4 * u] = v;
        }
    }

    float o[4][4];
    float m[4], l[4];
    #pragma unroll
    for (int i = 0; i < 4; i++) {
        m[i] = -1e30f; l[i] = 0.f;
        #pragma unroll
        for (int j = 0; j < 4; j++) o[i][j] = 0.f;
    }

    for (int kt = 0; kt <= qt; kt++) {
        {
            const int r  = t >> 2;
            const int db = (t & 3) * 16;
            const size_t gb = (size_t)(kt * 64 + r) * DK + db;
            #pragma unroll
            for (int u = 0; u < 4; u++) {
                float4 kv = *(const float4*)&Kb[gb + 4 * u];
                KsT[(db + 4 * u + 0) * AST + r] = kv.x;
                KsT[(db + 4 * u + 1) * AST + r] = kv.y;
                KsT[(db + 4 * u + 2) * AST + r] = kv.z;
                KsT[(db + 4 * u + 3) * AST + r] = kv.w;
                float4 vv = *(const float4*)&Vb[gb + 4 * u];
                *(float4*)&Vs[r * AST + db + 4 * u] = vv;
            }
        }
        __syncthreads();

        float sc[4][4];
        #pragma unroll
        for (int i = 0; i < 4; i++)
            #pragma unroll
            for (int j = 0; j < 4; j++) sc[i][j] = 0.f;

        #pragma unroll
        for (int d4 = 0; d4 < 16; d4++) {
            float qf[4][4];
            #pragma unroll
            for (int i = 0; i < 4; i++) {
                float4 qv = *(const float4*)&Qs[(4 * tr + i) * AST + 4 * d4];
                qf[i][0] = qv.x; qf[i][1] = qv.y; qf[i][2] = qv.z; qf[i][3] = qv.w;
            }
            #pragma unroll
            for (int u = 0; u < 4; u++) {
                float4 kv = *(const float4*)&KsT[(4 * d4 + u) * AST + 4 * tc];
                #pragma unroll
                for (int i = 0; i < 4; i++) {
                    sc[i][0] = fmaf(qf[i][u], kv.x, sc[i][0]);
                    sc[i][1] = fmaf(qf[i][u], kv.y, sc[i][1]);
                    sc[i][2] = fmaf(qf[i][u], kv.z, sc[i][2]);
                    sc[i][3] = fmaf(qf[i][u], kv.w, sc[i][3]);
                }
            }
        }

        {
            const int kjb = kt * 64 + 4 * tc;
            #pragma unroll
            for (int i = 0; i < 4; i++) {
                const int qi = q0 + 4 * tr + i;
                #pragma unroll
                for (int j = 0; j < 4; j++)
                    if (kjb + j >= qi) sc[i][j] = -1e30f;
            }
        }

        #pragma unroll
        for (int i = 0; i < 4; i++) {
            float mx = fmaxf(fmaxf(sc[i][0], sc[i][1]), fmaxf(sc[i][2], sc[i][3]));
            mx = rmax16(mx);
            const float mnew = fmaxf(m[i], mx);
            const float corr = __expf(m[i] - mnew);
            m[i] = mnew;
            float4 p;
            p.x = __expf(sc[i][0] - mnew);
            p.y = __expf(sc[i][1] - mnew);
            p.z = __expf(sc[i][2] - mnew);
            p.w = __expf(sc[i][3] - mnew);
            float rs = p.x + p.y + p.z + p.w;
            rs = rsum16(rs);
            l[i] = l[i] * corr + rs;
            #pragma unroll
            for (int j = 0; j < 4; j++) o[i][j] *= corr;
            *(float4*)&Ps[(4 * tr + i) * AST + 4 * tc] = p;
        }
        __syncthreads();

        #pragma unroll
        for (int k4 = 0; k4 < 16; k4++) {
            float pf[4][4];
            #pragma unroll
            for (int i = 0; i < 4; i++) {
                float4 pv = *(const float4*)&Ps[(4 * tr + i) * AST + 4 * k4];
                pf[i][0] = pv.x; pf[i][1] = pv.y; pf[i][2] = pv.z; pf[i][3] = pv.w;
            }
            #pragma unroll
            for (int u = 0; u < 4; u++) {
                float4 vv = *(const float4*)&Vs[(4 * k4 + u) * AST + 4 * tc];
                #pragma unroll
                for (int i = 0; i < 4; i++) {
                    o[i][0] = fmaf(pf[i][u], vv.x, o[i][0]);
                    o[i][1] = fmaf(pf[i][u], vv.y, o[i][1]);
                    o[i][2] = fmaf(pf[i][u], vv.z, o[i][2]);
                    o[i][3] = fmaf(pf[i][u], vv.w, o[i][3]);
                }
            }
        }
        __syncthreads();
    }

    const int b = bh >> 4, h = bh & 15;
    #pragma unroll
    for (int i = 0; i < 4; i++) {
        const int qi = q0 + 4 * tr + i;
        const float inv = (qi == 0) ? 0.f : (1.f / l[i]);
        float4 r;
        r.x = o[i][0] * inv; r.y = o[i][1] * inv;
        r.z = o[i][2] * inv; r.w = o[i][3] * inv;
        *(float4*)&ctx[((size_t)(b * SEQ + qi)) * D_MODEL + h * DK + 4 * tc] = r;
    }
}

// ---------------- layernorm ----------------
__global__ __launch_bounds__(256)
void ln_kernel(const float* __restrict__ X, const float* __restrict__ G,
               const float* __restrict__ Bt, float* __restrict__ O)
{
    __shared__ float ws[8], ws2[8];
    __shared__ float s_mu, s_rs;
    const int t = threadIdx.x;
    const size_t row = blockIdx.x;

    float4 v = *(const float4*)&X[row * D_MODEL + t * 4];
    float s  = v.x + v.y + v.z + v.w;
    float s2 = v.x * v.x + v.y * v.y + v.z * v.z + v.w * v.w;
    #pragma unroll
    for (int o = 16; o; o >>= 1) {
        s  += __shfl_xor_sync(0xffffffffu, s,  o);
        s2 += __shfl_xor_sync(0xffffffffu, s2, o);
    }
    if ((t & 31) == 0) { ws[t >> 5] = s; ws2[t >> 5] = s2; }
    __syncthreads();
    if (t == 0) {
        float S = 0.f, S2 = 0.f;
        #pragma unroll
        for (int w = 0; w < 8; w++) { S += ws[w]; S2 += ws2[w]; }
        const float mu  = S * (1.f / (float)D_MODEL);
        const float var = S2 * (1.f / (float)D_MODEL) - mu * mu;
        s_mu = mu;
        s_rs = rsqrtf(var + 1e-5f);
    }
    __syncthreads();
    const float mu = s_mu, rs = s_rs;

    float4 g = *(const float4*)&G[t * 4];
    float4 b = *(const float4*)&Bt[t * 4];
    float4 r;
    r.x = (v.x - mu) * rs * g.x + b.x;
    r.y = (v.y - mu) * rs * g.y + b.y;
    r.z = (v.z - mu) * rs * g.z + b.z;
    r.w = (v.w - mu) * rs * g.w + b.w;
    *(float4*)&O[row * D_MODEL + t * 4] = r;
}

// ---------------- orchestration ----------------
static inline void run_gemm_prep(const float* Aact, const float* W, int K, int N,
                                 __nv_bfloat16* abuf, __nv_bfloat16* wbuf)
{
    const int total4 = M_TOT * K / 4;
    act_split_kernel<<<(total4 + 255) / 256, 256>>>(Aact, abuf, K, total4);
    wt_split_kernel<<<dim3(K / 32, N / 32), 256>>>(W, wbuf, K, N);
}

extern "C" void kernel_launch(void* const* d_in, const int* in_sizes, int n_in,
                              void* d_out, int out_size)
{
    (void)in_sizes; (void)n_in; (void)out_size;

    const float* query = (const float*)d_in[0];
    const float* key_i = (const float*)d_in[1];
    const float* vals  = (const float*)d_in[2];
    const float* Wq = (const float*)d_in[3];
    const float* bq = (const float*)d_in[4];
    const float* Wk = (const float*)d_in[5];
    const float* bk = (const float*)d_in[6];
    const float* Wv = (const float*)d_in[7];
    const float* bv = (const float*)d_in[8];
    const float* Wo = (const float*)d_in[9];
    const float* bo = (const float*)d_in[10];
    const float* ln1g = (const float*)d_in[11];
    const float* ln1b = (const float*)d_in[12];
    const float* W1 = (const float*)d_in[13];
    const float* b1 = (const float*)d_in[14];
    const float* W2 = (const float*)d_in[15];
    const float* b2 = (const float*)d_in[16];
    const float* ln2g = (const float*)d_in[17];
    const float* ln2b = (const float*)d_in[18];
    float* out = (float*)d_out;

    float *pq, *pk, *pv, *pctx, *pt, *px, *ph;
    __nv_bfloat16 *pab, *pwb;
    cudaGetSymbolAddress((void**)&pq,   g_q);
    cudaGetSymbolAddress((void**)&pk,   g_k);
    cudaGetSymbolAddress((void**)&pv,   g_v);
    cudaGetSymbolAddress((void**)&pctx, g_ctx);
    cudaGetSymbolAddress((void**)&pt,   g_t);
    cudaGetSymbolAddress((void**)&px,   g_x);
    cudaGetSymbolAddress((void**)&ph,   g_h);
    cudaGetSymbolAddress((void**)&pab,  g_abuf);
    cudaGetSymbolAddress((void**)&pwb,  g_wbuf);

    cudaFuncSetAttribute(attn_kernel,
                         cudaFuncAttributeMaxDynamicSharedMemorySize, ATTN_SMEM);
    cudaFuncSetAttribute(tc_gemm<MODE_QKV>,
                         cudaFuncAttributeMaxDynamicSharedMemorySize, GEMM_SMEM);
    cudaFuncSetAttribute(tc_gemm<MODE_RELU>,
                         cudaFuncAttributeMaxDynamicSharedMemorySize, GEMM_SMEM);
    cudaFuncSetAttribute(tc_gemm<MODE_RES>,
                         cudaFuncAttributeMaxDynamicSharedMemorySize, GEMM_SMEM);

    const dim3 blk(256);
    const dim3 grid_1k(D_MODEL / 128, M_TOT / 128);   // (8, 32)
    const dim3 grid_4k(D_FF / 128,    M_TOT / 128);   // (32, 32)

    // QKV projections (bf16-split HMMA), scattered into [B,H,S,DK]
    run_gemm_prep(query, Wq, D_MODEL, D_MODEL, pab, pwb);
    tc_gemm<MODE_QKV><<<grid_1k, blk, GEMM_SMEM>>>(pab, pwb, bq, nullptr, pq, D_MODEL, 3 * D_MODEL);
    run_gemm_prep(key_i, Wk, D_MODEL, D_MODEL, pab, pwb);
    tc_gemm<MODE_QKV><<<grid_1k, blk, GEMM_SMEM>>>(pab, pwb, bk, nullptr, pk, D_MODEL, 3 * D_MODEL);
    run_gemm_prep(vals, Wv, D_MODEL, D_MODEL, pab, pwb);
    tc_gemm<MODE_QKV><<<grid_1k, blk, GEMM_SMEM>>>(pab, pwb, bv, nullptr, pv, D_MODEL, 3 * D_MODEL);

    // causal flash attention -> ctx [B,S,D]
    attn_kernel<<<dim3(SEQ / 64, NB * NH), blk, ATTN_SMEM>>>(pq, pk, pv, pctx);

    // attn_out = ctx @ Wo + bo + query -> g_t ; LN1 -> g_x
    run_gemm_prep(pctx, Wo, D_MODEL, D_MODEL, pab, pwb);
    tc_gemm<MODE_RES><<<grid_1k, blk, GEMM_SMEM>>>(pab, pwb, bo, query, pt, D_MODEL, 3 * D_MODEL);
    ln_kernel<<<M_TOT, 256>>>(pt, ln1g, ln1b, px);

    // FFN: h = relu(x @ W1 + b1) ; y = h @ W2 + b2 + x ; LN2 -> out
    run_gemm_prep(px, W1, D_MODEL, D_FF, pab, pwb);
    tc_gemm<MODE_RELU><<<grid_4k, blk, GEMM_SMEM>>>(pab, pwb, b1, nullptr, ph, D_FF, 3 * D_MODEL);
    run_gemm_prep(ph, W2, D_FF, D_MODEL, pab, pwb);
    tc_gemm<MODE_RES><<<grid_1k, blk, GEMM_SMEM>>>(pab, pwb, b2, px, pt, D_MODEL, 3 * D_FF);
    ln_kernel<<<M_TOT, 256>>>(pt, ln2g, ln2b, out);
}